// round 2
// baseline (speedup 1.0000x reference)
#include <cuda_runtime.h>
#include <cstdint>
#include <cstddef>

#define HID   128
#define MAXN  50000
#define MAXE  800000

// Scratch (device globals: allocation-free rule)
__device__ __align__(16) float    g_AB[(size_t)MAXN * 256];  // [N,256]: cols 0..127 = A = z@Wm_top, 128..255 = B = z@Wm_mid
__device__ __align__(16) unsigned g_S [(size_t)MAXN * HID];  // ordered-uint max keys
__device__ __align__(16) float    g_M [(size_t)MAXN * HID];  // m matrix

// ---------------------------------------------------------------------------
// init: S keys <- 0  (0 is below every real key; real keys are > 0)
// ---------------------------------------------------------------------------
__global__ void init_S(int total) {
    int i = blockIdx.x * blockDim.x + threadIdx.x;
    if (i < total) g_S[i] = 0u;
}

// ---------------------------------------------------------------------------
// SGEMM: C[m0.., colOff..colOff+127] = Atile @ W(+blockIdx.y*128*128) [+bias]
// BM=64, BN=128, BK=64, 256 threads, TM=4 x TN=(4+4 split cols)
// A source: cols k<128 from A0, k>=128 from A1 (both row-major ld=128)
// ---------------------------------------------------------------------------
__global__ __launch_bounds__(256) void sgemm64x128(
    const float* __restrict__ A0, const float* __restrict__ A1,
    const float* __restrict__ W,  const float* __restrict__ bias,
    float* __restrict__ C, int Mrows, int K, int ldC)
{
    __shared__ float As[64][68];    // [m][k], padded
    __shared__ float Bs[64][128];   // [k][n]

    const int tid = threadIdx.x;
    const int tx = tid & 15, ty = tid >> 4;
    const int m0 = blockIdx.x * 64;
    const float* Wp = W + (size_t)blockIdx.y * (128 * 128);
    const int colOff = blockIdx.y * 128;

    float acc[4][8];
#pragma unroll
    for (int i = 0; i < 4; i++)
#pragma unroll
        for (int j = 0; j < 8; j++) acc[i][j] = 0.f;

    const int nkt = K >> 6;
    for (int kt = 0; kt < nkt; ++kt) {
        const float* Ap; int kbase;
        if (kt * 64 < 128) { Ap = A0; kbase = kt * 64; }
        else               { Ap = A1; kbase = kt * 64 - 128; }

        // A tile: 64 rows x 64 k
#pragma unroll
        for (int p = 0; p < 4; p++) {
            int l = tid + p * 256;
            int r = l >> 4, kg = (l & 15) * 4;
            int g = m0 + r;
            float4 v = make_float4(0.f, 0.f, 0.f, 0.f);
            if (g < Mrows) v = *(const float4*)&Ap[(size_t)g * 128 + kbase + kg];
            *(float4*)&As[r][kg] = v;
        }
        // W tile: 64 k x 128 n
#pragma unroll
        for (int p = 0; p < 8; p++) {
            int l = tid + p * 256;
            int kr = l >> 5, c = (l & 31) * 4;
            *(float4*)&Bs[kr][c] = *(const float4*)&Wp[(size_t)(kt * 64 + kr) * 128 + c];
        }
        __syncthreads();

#pragma unroll 8
        for (int kk = 0; kk < 64; ++kk) {
            float a[4];
#pragma unroll
            for (int i = 0; i < 4; i++) a[i] = As[ty * 4 + i][kk];
            float4 b0 = *(float4*)&Bs[kk][tx * 4];
            float4 b1 = *(float4*)&Bs[kk][64 + tx * 4];
#pragma unroll
            for (int i = 0; i < 4; i++) {
                acc[i][0] += a[i] * b0.x; acc[i][1] += a[i] * b0.y;
                acc[i][2] += a[i] * b0.z; acc[i][3] += a[i] * b0.w;
                acc[i][4] += a[i] * b1.x; acc[i][5] += a[i] * b1.y;
                acc[i][6] += a[i] * b1.z; acc[i][7] += a[i] * b1.w;
            }
        }
        __syncthreads();
    }

    float4 bv0 = make_float4(0.f, 0.f, 0.f, 0.f), bv1 = bv0;
    if (bias) {
        bv0 = *(const float4*)&bias[tx * 4];
        bv1 = *(const float4*)&bias[64 + tx * 4];
    }
#pragma unroll
    for (int i = 0; i < 4; i++) {
        int g = m0 + ty * 4 + i;
        if (g < Mrows) {
            float4 o0 = make_float4(acc[i][0] + bv0.x, acc[i][1] + bv0.y,
                                    acc[i][2] + bv0.z, acc[i][3] + bv0.w);
            float4 o1 = make_float4(acc[i][4] + bv1.x, acc[i][5] + bv1.y,
                                    acc[i][6] + bv1.z, acc[i][7] + bv1.w);
            *(float4*)&C[(size_t)g * ldC + colOff + tx * 4]      = o0;
            *(float4*)&C[(size_t)g * ldC + colOff + 64 + tx * 4] = o1;
        }
    }
}

// ---------------------------------------------------------------------------
// edge kernel: one warp per edge. v = B[src] + w*r ; atomicMax keys into S[dst].
// Monotone uint encoding so atomicMax(uint) == float max. Cached-read filter
// skips atomics that cannot win (safe: keys only grow).
// ---------------------------------------------------------------------------
__device__ __forceinline__ unsigned f2key(float f) {
    unsigned u = __float_as_uint(f);
    return (u & 0x80000000u) ? ~u : (u | 0x80000000u);
}

__global__ void edge_max(const int* __restrict__ src, const int* __restrict__ dst,
                         const float* __restrict__ w, const float* __restrict__ r,
                         int E)
{
    int warp = (blockIdx.x * blockDim.x + threadIdx.x) >> 5;
    int lane = threadIdx.x & 31;
    if (warp >= E) return;
    int s = __ldg(&src[warp]);
    int d = __ldg(&dst[warp]);
    float ww = __ldg(&w[warp]);
    float4 b  = *(const float4*)&g_AB[(size_t)s * 256 + 128 + lane * 4];
    float4 rv = *(const float4*)&r[lane * 4];
    float v0 = fmaf(ww, rv.x, b.x);
    float v1 = fmaf(ww, rv.y, b.y);
    float v2 = fmaf(ww, rv.z, b.z);
    float v3 = fmaf(ww, rv.w, b.w);
    unsigned* Sp = &g_S[(size_t)d * 128 + lane * 4];
    unsigned k0 = f2key(v0), k1 = f2key(v1), k2 = f2key(v2), k3 = f2key(v3);
    if (k0 > Sp[0]) atomicMax(&Sp[0], k0);
    if (k1 > Sp[1]) atomicMax(&Sp[1], k1);
    if (k2 > Sp[2]) atomicMax(&Sp[2], k2);
    if (k3 > Sp[3]) atomicMax(&Sp[3], k3);
}

// ---------------------------------------------------------------------------
// convert: m[d,c] = (no edge) ? 0 : decode(S) + A[d,c] + bm[c]
// ---------------------------------------------------------------------------
__global__ void convert_S(const float* __restrict__ bm, int total) {
    int i = blockIdx.x * blockDim.x + threadIdx.x;
    if (i >= total) return;
    unsigned k = g_S[i];
    float m = 0.f;
    if (k) {
        float dec = (k & 0x80000000u) ? __uint_as_float(k ^ 0x80000000u)
                                      : __uint_as_float(~k);
        int d = i >> 7, c = i & 127;
        m = dec + g_AB[(size_t)d * 256 + c] + bm[c];
    }
    g_M[i] = m;
}

// ---------------------------------------------------------------------------
extern "C" void kernel_launch(void* const* d_in, const int* in_sizes, int n_in,
                              void* d_out, int out_size)
{
    const float* z   = (const float*)d_in[0];
    const float* w   = (const float*)d_in[1];
    const int*   src = (const int*)  d_in[2];
    const int*   dst = (const int*)  d_in[3];
    const float* Wm  = (const float*)d_in[4];
    const float* bm  = (const float*)d_in[5];
    const float* Wu  = (const float*)d_in[6];
    const float* bu  = (const float*)d_in[7];
    float* out = (float*)d_out;

    int n = in_sizes[0] / HID;
    int E = in_sizes[1];
    if (n > MAXN) n = MAXN;
    if (E > MAXE) E = MAXE;

    float*    AB = nullptr;
    float*    M  = nullptr;
    cudaGetSymbolAddress((void**)&AB, g_AB);
    cudaGetSymbolAddress((void**)&M,  g_M);

    // 1. init S keys
    {
        int total = n * HID;
        init_S<<<(total + 511) / 512, 512>>>(total);
    }
    // 2. AB = z @ Wm[0:256]  ([N,256]; col-block 1 uses Wm rows 128..255)
    {
        dim3 grid((n + 63) / 64, 2);
        sgemm64x128<<<grid, 256>>>(z, nullptr, Wm, nullptr, AB, n, 128, 256);
    }
    // 3. per-edge max into S
    {
        const float* r = Wm + (size_t)256 * 128;  // last row of Wm
        int blocks = (E + 7) / 8;                 // 8 warps / block
        edge_max<<<blocks, 256>>>(src, dst, w, r, E);
    }
    // 4. S -> m  (adds A[d] + bm, empty segments -> 0)
    {
        int total = n * HID;
        convert_S<<<(total + 255) / 256, 256>>>(bm, total);
    }
    // 5. h = concat(z, m) @ Wu + bu
    {
        dim3 grid((n + 63) / 64, 1);
        sgemm64x128<<<grid, 256>>>(z, M, Wu, bu, out, n, 256, HID);
    }
}